// round 13
// baseline (speedup 1.0000x reference)
#include <cuda_runtime.h>
#include <cuda_bf16.h>

// Problem constants
#define BATCH    1024
#define P784     784
#define CATW     848            // 784 + 32 + 32

typedef unsigned long long ull;  // f32x2 container (two samples per register)

// Scratch (allocation-free rule: __device__ global)
__device__ float g_cat[BATCH * CATW];   // [1024, 848] concat rows

// ---- packed f32x2 helpers (Blackwell sm_103a) ----
__device__ __forceinline__ ull pk2(float a, float b) {
    ull r; asm("mov.b64 %0, {%1, %2};" : "=l"(r) : "f"(a), "f"(b)); return r;
}
__device__ __forceinline__ void up2(float& a, float& b, ull v) {
    asm("mov.b64 {%0, %1}, %2;" : "=f"(a), "=f"(b) : "l"(v));
}
__device__ __forceinline__ ull fma2(ull a, ull b, ull c) {
    ull d; asm("fma.rn.f32x2 %0, %1, %2, %3;" : "=l"(d) : "l"(a), "l"(b), "l"(c)); return d;
}
__device__ __forceinline__ ull add2(ull a, ull b) {
    ull d; asm("add.rn.f32x2 %0, %1, %2;" : "=l"(d) : "l"(a), "l"(b)); return d;
}
__device__ __forceinline__ ull relu2(ull v) {
    float a, b; up2(a, b, v);
    return pk2(fmaxf(a, 0.f), fmaxf(b, 0.f));
}

// ---------------------------------------------------------------------------
// Kernel 1: fused conv branch + landscape branches, TWO samples per block
//   packed in f32x2 lanes. grid = 512 blocks, 128 threads (4 warps).
//   Warp w owns output rows [7w, 7w+7); lane = column (lanes 28-31 idle).
//   conv1 -> h1 in registers; conv2 accumulates per-column partials
//   Pa/Pm/Pb (destined right/center/left) so column halos are exchanged by
//   shuffle ONCE at the end instead of per channel.
//   landscape: tent(v,t) monotone non-increasing in v => only (min1,min2,max).
// ---------------------------------------------------------------------------
__global__ void __launch_bounds__(128)
k_fused(const float* __restrict__ x,
        const float* __restrict__ dtm1,
        const float* __restrict__ dtm2,
        const float* __restrict__ w1g, const float* __restrict__ b1g,
        const float* __restrict__ w2g, const float* __restrict__ b2g,
        const float* __restrict__ g1w, const float* __restrict__ g1b,
        const float* __restrict__ g2w, const float* __restrict__ g2b)
{
    __shared__ __align__(16) ull w1d[32][10];     // [ch][tap0..8, 9=bias], duplicated pairs
    __shared__ __align__(16) ull w2d[32][10];     // [ch][tap0..8]
    __shared__ float part[4][4][3];               // (samp*2+br), warp, (m1,m2,mx)
    __shared__ float Ls[2][2][64];                // [samp][br][64]

    const int tid  = threadIdx.x;
    const int b0   = blockIdx.x * 2;
    const int b1   = b0 + 1;
    const int wid  = tid >> 5;
    const int lane = tid & 31;
    const unsigned FULL = 0xffffffffu;

    // stage weights transposed + duplicated into both f32x2 lanes
    for (int i = tid; i < 288; i += 128) {
        int tap = i / 32, c = i % 32;
        float a = w1g[i], b = w2g[i];
        w1d[c][tap] = pk2(a, a);
        w2d[c][tap] = pk2(b, b);
    }
    if (tid < 32) { float v = b1g[tid]; w1d[tid][9] = pk2(v, v); }

    // ---- input rows into registers (rows r0-2 .. r0+8, zero-padded) ----
    const int r0 = wid * 7;
    const int c  = lane;
    ull xc[11], xl[11], xr[11];
    #pragma unroll
    for (int j = 0; j < 11; j++) {
        int row = r0 - 2 + j;
        float v0 = 0.f, v1 = 0.f;
        if (row >= 0 && row < 28 && c < 28) {
            v0 = x[b0 * P784 + row * 28 + c];
            v1 = x[b1 * P784 + row * 28 + c];
        }
        xc[j] = pk2(v0, v1);
    }
    #pragma unroll
    for (int j = 0; j < 11; j++) {
        ull u = __shfl_up_sync  (FULL, xc[j], 1);
        ull d = __shfl_down_sync(FULL, xc[j], 1);
        xl[j] = (lane == 0)  ? 0ULL : u;
        xr[j] = (lane >= 27) ? 0ULL : d;
    }

    // ---- landscape partial reductions (4 = 2 samples x 2 branches) ----
    #pragma unroll
    for (int pe = 0; pe < 4; pe++) {
        int samp = pe >> 1, br = pe & 1;
        const float* v = (br ? dtm2 : dtm1) + (b0 + samp) * P784;
        float m1 = 1e30f, m2 = 1e30f, mx = -1e30f;
        for (int i = tid; i < P784; i += 128) {
            float f = v[i];
            mx = fmaxf(mx, f);
            if (f < m1) { m2 = m1; m1 = f; }
            else        { m2 = fminf(m2, f); }
        }
        #pragma unroll
        for (int o = 16; o > 0; o >>= 1) {
            float o1 = __shfl_down_sync(FULL, m1, o);
            float o2 = __shfl_down_sync(FULL, m2, o);
            float ox = __shfl_down_sync(FULL, mx, o);
            float nm1 = fminf(m1, o1);
            float nm2 = fminf(fmaxf(m1, o1), fminf(m2, o2));
            m1 = nm1; m2 = nm2; mx = fmaxf(mx, ox);
        }
        if (lane == 0) { part[pe][wid][0] = m1; part[pe][wid][1] = m2; part[pe][wid][2] = mx; }
    }
    __syncthreads();   // weights + partials visible

    const float b2v = __ldg(b2g);
    ull Pa[7], Pm[7], Pb[7];
    const ull b2p = pk2(b2v, b2v);
    #pragma unroll
    for (int i = 0; i < 7; i++) { Pa[i] = 0ULL; Pm[i] = b2p; Pb[i] = 0ULL; }

    // ---- channel loop: pure register f32x2, no shuffles, no barriers ----
    #pragma unroll 1
    for (int ch = 0; ch < 32; ch++) {
        const ull* W1c = w1d[ch];
        ull h1[9];
        #pragma unroll
        for (int j = 0; j < 9; j++) {
            int row = r0 - 1 + j;
            ull s = W1c[9];
            s = fma2(xl[j    ], W1c[0], s);
            s = fma2(xc[j    ], W1c[1], s);
            s = fma2(xr[j    ], W1c[2], s);
            s = fma2(xl[j + 1], W1c[3], s);
            s = fma2(xc[j + 1], W1c[4], s);
            s = fma2(xr[j + 1], W1c[5], s);
            s = fma2(xl[j + 2], W1c[6], s);
            s = fma2(xc[j + 2], W1c[7], s);
            s = fma2(xr[j + 2], W1c[8], s);
            h1[j] = (row >= 0 && row < 28) ? relu2(s) : 0ULL;
        }
        const ull* W2c = w2d[ch];
        #pragma unroll
        for (int j = 0; j < 9; j++) {
            #pragma unroll
            for (int dr = 0; dr < 3; dr++) {
                int i = j - dr;                 // output row index
                if (i >= 0 && i < 7) {
                    Pa[i] = fma2(h1[j], W2c[dr * 3 + 0], Pa[i]);  // -> column c+1
                    Pm[i] = fma2(h1[j], W2c[dr * 3 + 1], Pm[i]);  // -> column c
                    Pb[i] = fma2(h1[j], W2c[dr * 3 + 2], Pb[i]);  // -> column c-1
                }
            }
        }
    }

    // ---- column-halo exchange ONCE + store (relu) ----
    #pragma unroll
    for (int i = 0; i < 7; i++) {
        ull au = __shfl_up_sync  (FULL, Pa[i], 1);   // from column c-1
        ull bd = __shfl_down_sync(FULL, Pb[i], 1);   // from column c+1
        ull al = (lane == 0)  ? 0ULL : au;
        ull br = (lane >= 27) ? 0ULL : bd;
        ull tot = add2(Pm[i], add2(al, br));
        if (c < 28) {
            float o0, o1; up2(o0, o1, tot);
            g_cat[b0 * CATW + (r0 + i) * 28 + c] = fmaxf(o0, 0.f);
            g_cat[b1 * CATW + (r0 + i) * 28 + c] = fmaxf(o1, 0.f);
        }
    }

    __syncthreads();   // landscape partials from all warps

    // tents: 256 values (2 samp x 2 br x 64) over 128 threads
    #pragma unroll
    for (int rep = 0; rep < 2; rep++) {
        int e = tid + rep * 128;
        int samp = e >> 7, br = (e >> 6) & 1, q = e & 63;
        int k = q >> 5, ti = q & 31;
        int pe = samp * 2 + br;
        float M1 = part[pe][0][0], M2 = part[pe][0][1], MX = part[pe][0][2];
        #pragma unroll
        for (int w = 1; w < 4; w++) {
            float a1 = part[pe][w][0], a2 = part[pe][w][1], ax = part[pe][w][2];
            float n1 = fminf(M1, a1);
            float n2 = fminf(fmaxf(M1, a1), fminf(M2, a2));
            M1 = n1; M2 = n2; MX = fmaxf(MX, ax);
        }
        float t0 = (br == 0) ? 0.01f : 0.05f;
        float dt = (br == 0) ? (0.28f / 31.0f) : (0.25f / 31.0f);
        float t  = t0 + (float)ti * dt;
        float vk = k ? M2 : M1;
        Ls[samp][br][q] = fmaxf(0.f, fminf(t - vk, MX - t));
    }
    __syncthreads();

    // branch GEMMs: 2 samples x [64] @ [64,32] + bias, relu  (128 threads)
    {
        int samp = tid >> 6, br = (tid >> 5) & 1, f = tid & 31;
        const float* gw = br ? g2w : g1w;
        float s = br ? g2b[f] : g1b[f];
        #pragma unroll
        for (int j = 0; j < 64; j++) s += Ls[samp][br][j] * gw[j * 32 + f];
        g_cat[(b0 + samp) * CATW + 784 + br * 32 + f] = fmaxf(s, 0.f);
    }
}

// ---------------------------------------------------------------------------
// Kernel 2: fused fc1 + relu + fc2.  grid = 128 blocks x 8 samples, 256 thr.
//   No split-K, no atomics. A tile staged transposed in smem (pad 10 so the
//   float2 sample-pair load is 8B-aligned); W1 streamed coalesced from L1/L2.
// ---------------------------------------------------------------------------
__global__ void __launch_bounds__(256)
k_fc(const float* __restrict__ W1, const float* __restrict__ fc1b,
     const float* __restrict__ W2, const float* __restrict__ fc2b,
     float* __restrict__ out)
{
    __shared__ __align__(16) float As[848 * 10];   // [k][sample], pad 10
    __shared__ float zs[8 * 64];

    const int tid = threadIdx.x;
    const int m0  = blockIdx.x * 8;

    // stage A transposed: warp per sample, coalesced reads
    {
        int si = tid >> 5, ln = tid & 31;
        const float* src = g_cat + (m0 + si) * CATW;
        for (int k = ln; k < 848; k += 32)
            As[k * 10 + si] = src[k];
    }
    __syncthreads();

    const int q = tid >> 6;    // sample pair: (2q, 2q+1)
    const int f = tid & 63;

    float acc0 = 0.f, acc1 = 0.f;
    #pragma unroll 8
    for (int k = 0; k < 848; k++) {
        float w  = W1[k * 64 + f];                          // coalesced LDG
        float2 a = *(const float2*)&As[k * 10 + 2 * q];     // broadcast LDS.64
        acc0 += a.x * w;
        acc1 += a.y * w;
    }

    float bb = fc1b[f];
    zs[(2 * q    ) * 64 + f] = fmaxf(acc0 + bb, 0.f);
    zs[(2 * q + 1) * 64 + f] = fmaxf(acc1 + bb, 0.f);
    __syncthreads();

    if (tid < 80) {
        int m = tid / 10, cc = tid - m * 10;
        float s = fc2b[cc];
        #pragma unroll
        for (int j = 0; j < 64; j++) s += zs[m * 64 + j] * W2[j * 10 + cc];
        out[(m0 + m) * 10 + cc] = s;
    }
}

// ---------------------------------------------------------------------------
extern "C" void kernel_launch(void* const* d_in, const int* in_sizes, int n_in,
                              void* d_out, int out_size)
{
    (void)in_sizes; (void)n_in; (void)out_size;
    const float* x    = (const float*)d_in[0];
    const float* dtm1 = (const float*)d_in[1];
    const float* dtm2 = (const float*)d_in[2];
    const float* w1   = (const float*)d_in[3];
    const float* b1   = (const float*)d_in[4];
    const float* w2   = (const float*)d_in[5];
    const float* b2   = (const float*)d_in[6];
    const float* g1w  = (const float*)d_in[7];
    const float* g1b  = (const float*)d_in[8];
    const float* g2w  = (const float*)d_in[9];
    const float* g2b  = (const float*)d_in[10];
    const float* fc1w = (const float*)d_in[11];
    const float* fc1b = (const float*)d_in[12];
    const float* fc2w = (const float*)d_in[13];
    const float* fc2b = (const float*)d_in[14];
    float* out = (float*)d_out;

    k_fused<<<BATCH / 2, 128>>>(x, dtm1, dtm2, w1, b1, w2, b2, g1w, g1b, g2w, g2b);
    k_fc<<<BATCH / 8, 256>>>(fc1w, fc1b, fc2w, fc2b, out);
}

// round 14
// speedup vs baseline: 1.1493x; 1.1493x over previous
#include <cuda_runtime.h>
#include <cuda_bf16.h>

// Problem constants
#define BATCH    1024
#define P784     784
#define CATW     848            // 784 + 32 + 32

typedef unsigned long long ull;  // f32x2 container (two fp32 lanes per register)

// Scratch (allocation-free rule: __device__ globals)
__device__ float g_cat [BATCH * CATW];   // [1024, 848] concat rows
__device__ float g_zacc[BATCH * 64];     // fc1 pre-activation accumulator

// ---- packed f32x2 helpers (Blackwell sm_103a) ----
__device__ __forceinline__ ull pk2(float a, float b) {
    ull r; asm("mov.b64 %0, {%1, %2};" : "=l"(r) : "f"(a), "f"(b)); return r;
}
__device__ __forceinline__ void up2(float& a, float& b, ull v) {
    asm("mov.b64 {%0, %1}, %2;" : "=f"(a), "=f"(b) : "l"(v));
}
__device__ __forceinline__ ull fma2(ull a, ull b, ull c) {
    ull d; asm("fma.rn.f32x2 %0, %1, %2, %3;" : "=l"(d) : "l"(a), "l"(b), "l"(c)); return d;
}
__device__ __forceinline__ ull add2(ull a, ull b) {
    ull d; asm("add.rn.f32x2 %0, %1, %2;" : "=l"(d) : "l"(a), "l"(b)); return d;
}
__device__ __forceinline__ ull relu2(ull v) {
    float a, b; up2(a, b, v);
    return pk2(fmaxf(a, 0.f), fmaxf(b, 0.f));
}

// ---------------------------------------------------------------------------
// Kernel 1: fused conv branch + landscape branches, TWO samples per block
//   packed in f32x2 lanes. grid = 512 blocks, 128 threads (4 warps).
//   (unchanged from round 13 — measured ~7.4us — plus g_zacc zeroing)
// ---------------------------------------------------------------------------
__global__ void __launch_bounds__(128)
k_fused(const float* __restrict__ x,
        const float* __restrict__ dtm1,
        const float* __restrict__ dtm2,
        const float* __restrict__ w1g, const float* __restrict__ b1g,
        const float* __restrict__ w2g, const float* __restrict__ b2g,
        const float* __restrict__ g1w, const float* __restrict__ g1b,
        const float* __restrict__ g2w, const float* __restrict__ g2b)
{
    __shared__ __align__(16) ull w1d[32][10];     // [ch][tap0..8, 9=bias], dup pairs
    __shared__ __align__(16) ull w2d[32][10];     // [ch][tap0..8]
    __shared__ float part[4][4][3];               // (samp*2+br), warp, (m1,m2,mx)
    __shared__ float Ls[2][2][64];                // [samp][br][64]

    const int tid  = threadIdx.x;
    const int b0   = blockIdx.x * 2;
    const int b1   = b0 + 1;
    const int wid  = tid >> 5;
    const int lane = tid & 31;
    const unsigned FULL = 0xffffffffu;

    // zero fc1 accumulator rows for both samples (consumed by k_fc1)
    g_zacc[b0 * 64 + tid] = 0.f;

    // stage weights transposed + duplicated into both f32x2 lanes
    for (int i = tid; i < 288; i += 128) {
        int tap = i / 32, c = i % 32;
        float a = w1g[i], b = w2g[i];
        w1d[c][tap] = pk2(a, a);
        w2d[c][tap] = pk2(b, b);
    }
    if (tid < 32) { float v = b1g[tid]; w1d[tid][9] = pk2(v, v); }

    // ---- input rows into registers (rows r0-2 .. r0+8, zero-padded) ----
    const int r0 = wid * 7;
    const int c  = lane;
    ull xc[11], xl[11], xr[11];
    #pragma unroll
    for (int j = 0; j < 11; j++) {
        int row = r0 - 2 + j;
        float v0 = 0.f, v1 = 0.f;
        if (row >= 0 && row < 28 && c < 28) {
            v0 = x[b0 * P784 + row * 28 + c];
            v1 = x[b1 * P784 + row * 28 + c];
        }
        xc[j] = pk2(v0, v1);
    }
    #pragma unroll
    for (int j = 0; j < 11; j++) {
        ull u = __shfl_up_sync  (FULL, xc[j], 1);
        ull d = __shfl_down_sync(FULL, xc[j], 1);
        xl[j] = (lane == 0)  ? 0ULL : u;
        xr[j] = (lane >= 27) ? 0ULL : d;
    }

    // ---- landscape partial reductions (4 = 2 samples x 2 branches) ----
    #pragma unroll
    for (int pe = 0; pe < 4; pe++) {
        int samp = pe >> 1, br = pe & 1;
        const float* v = (br ? dtm2 : dtm1) + (b0 + samp) * P784;
        float m1 = 1e30f, m2 = 1e30f, mx = -1e30f;
        for (int i = tid; i < P784; i += 128) {
            float f = v[i];
            mx = fmaxf(mx, f);
            if (f < m1) { m2 = m1; m1 = f; }
            else        { m2 = fminf(m2, f); }
        }
        #pragma unroll
        for (int o = 16; o > 0; o >>= 1) {
            float o1 = __shfl_down_sync(FULL, m1, o);
            float o2 = __shfl_down_sync(FULL, m2, o);
            float ox = __shfl_down_sync(FULL, mx, o);
            float nm1 = fminf(m1, o1);
            float nm2 = fminf(fmaxf(m1, o1), fminf(m2, o2));
            m1 = nm1; m2 = nm2; mx = fmaxf(mx, ox);
        }
        if (lane == 0) { part[pe][wid][0] = m1; part[pe][wid][1] = m2; part[pe][wid][2] = mx; }
    }
    __syncthreads();   // weights + partials visible

    const float b2v = __ldg(b2g);
    ull Pa[7], Pm[7], Pb[7];
    const ull b2p = pk2(b2v, b2v);
    #pragma unroll
    for (int i = 0; i < 7; i++) { Pa[i] = 0ULL; Pm[i] = b2p; Pb[i] = 0ULL; }

    // ---- channel loop: pure register f32x2, no shuffles, no barriers ----
    #pragma unroll 1
    for (int ch = 0; ch < 32; ch++) {
        const ull* W1c = w1d[ch];
        ull h1[9];
        #pragma unroll
        for (int j = 0; j < 9; j++) {
            int row = r0 - 1 + j;
            ull s = W1c[9];
            s = fma2(xl[j    ], W1c[0], s);
            s = fma2(xc[j    ], W1c[1], s);
            s = fma2(xr[j    ], W1c[2], s);
            s = fma2(xl[j + 1], W1c[3], s);
            s = fma2(xc[j + 1], W1c[4], s);
            s = fma2(xr[j + 1], W1c[5], s);
            s = fma2(xl[j + 2], W1c[6], s);
            s = fma2(xc[j + 2], W1c[7], s);
            s = fma2(xr[j + 2], W1c[8], s);
            h1[j] = (row >= 0 && row < 28) ? relu2(s) : 0ULL;
        }
        const ull* W2c = w2d[ch];
        #pragma unroll
        for (int j = 0; j < 9; j++) {
            #pragma unroll
            for (int dr = 0; dr < 3; dr++) {
                int i = j - dr;                 // output row index
                if (i >= 0 && i < 7) {
                    Pa[i] = fma2(h1[j], W2c[dr * 3 + 0], Pa[i]);  // -> column c+1
                    Pm[i] = fma2(h1[j], W2c[dr * 3 + 1], Pm[i]);  // -> column c
                    Pb[i] = fma2(h1[j], W2c[dr * 3 + 2], Pb[i]);  // -> column c-1
                }
            }
        }
    }

    // ---- column-halo exchange ONCE + store (relu) ----
    #pragma unroll
    for (int i = 0; i < 7; i++) {
        ull au = __shfl_up_sync  (FULL, Pa[i], 1);   // from column c-1
        ull bd = __shfl_down_sync(FULL, Pb[i], 1);   // from column c+1
        ull al = (lane == 0)  ? 0ULL : au;
        ull br = (lane >= 27) ? 0ULL : bd;
        ull tot = add2(Pm[i], add2(al, br));
        if (c < 28) {
            float o0, o1; up2(o0, o1, tot);
            g_cat[b0 * CATW + (r0 + i) * 28 + c] = fmaxf(o0, 0.f);
            g_cat[b1 * CATW + (r0 + i) * 28 + c] = fmaxf(o1, 0.f);
        }
    }

    __syncthreads();   // landscape partials from all warps

    // tents: 256 values (2 samp x 2 br x 64) over 128 threads
    #pragma unroll
    for (int rep = 0; rep < 2; rep++) {
        int e = tid + rep * 128;
        int samp = e >> 7, br = (e >> 6) & 1, q = e & 63;
        int k = q >> 5, ti = q & 31;
        int pe = samp * 2 + br;
        float M1 = part[pe][0][0], M2 = part[pe][0][1], MX = part[pe][0][2];
        #pragma unroll
        for (int w = 1; w < 4; w++) {
            float a1 = part[pe][w][0], a2 = part[pe][w][1], ax = part[pe][w][2];
            float n1 = fminf(M1, a1);
            float n2 = fminf(fmaxf(M1, a1), fminf(M2, a2));
            M1 = n1; M2 = n2; MX = fmaxf(MX, ax);
        }
        float t0 = (br == 0) ? 0.01f : 0.05f;
        float dt = (br == 0) ? (0.28f / 31.0f) : (0.25f / 31.0f);
        float t  = t0 + (float)ti * dt;
        float vk = k ? M2 : M1;
        Ls[samp][br][q] = fmaxf(0.f, fminf(t - vk, MX - t));
    }
    __syncthreads();

    // branch GEMMs: 2 samples x [64] @ [64,32] + bias, relu  (128 threads)
    {
        int samp = tid >> 6, br = (tid >> 5) & 1, f = tid & 31;
        const float* gw = br ? g2w : g1w;
        float s = br ? g2b[f] : g1b[f];
        #pragma unroll
        for (int j = 0; j < 64; j++) s += Ls[samp][br][j] * gw[j * 32 + f];
        g_cat[(b0 + samp) * CATW + 784 + br * 32 + f] = fmaxf(s, 0.f);
    }
}

// ---------------------------------------------------------------------------
// Kernel 2: fc1 split-K GEMM with f32x2 m-packing.
//   [1024,848] @ [848,64] -> atomicAdd into g_zacc.
//   grid = (16 m-tiles of 64) x (16 k-chunks of 53); 256 thr.
//   Thread computes 4m x 4n as two f32x2 m-pair accumulators per n.
//   B tile pre-duplicated into both f32x2 lanes in smem.
// ---------------------------------------------------------------------------
__global__ void __launch_bounds__(256)
k_fc1(const float* __restrict__ W1)
{
    __shared__ __align__(16) float At [53 * 68];  // A^T: [k][m], stride 68
    __shared__ __align__(16) ull   Bsd[53 * 64];  // [k][f], duplicated pairs

    const int tid = threadIdx.x;
    const int m0  = blockIdx.x * 64;
    const int k0  = blockIdx.y * 53;
    const int tm  = tid & 15;
    const int tf  = tid >> 4;

    for (int e = tid; e < 53 * 64; e += 256) {
        int i = e / 53, j = e - i * 53;
        At[j * 68 + i] = g_cat[(m0 + i) * CATW + k0 + j];
    }
    for (int e = tid; e < 53 * 64; e += 256) {
        int j = e >> 6, q = e & 63;
        float w = W1[(k0 + j) * 64 + q];        // coalesced
        Bsd[j * 64 + q] = pk2(w, w);
    }
    __syncthreads();

    ull c01[4] = {0ULL, 0ULL, 0ULL, 0ULL};
    ull c23[4] = {0ULL, 0ULL, 0ULL, 0ULL};
    #pragma unroll 4
    for (int k = 0; k < 53; k++) {
        float4 a = *(const float4*)&At[k * 68 + tm * 4];
        ull a01 = pk2(a.x, a.y);
        ull a23 = pk2(a.z, a.w);
        const ull* bp = &Bsd[k * 64 + tf * 4];
        #pragma unroll
        for (int q = 0; q < 4; q++) {
            ull b = bp[q];                       // broadcast LDS
            c01[q] = fma2(a01, b, c01[q]);
            c23[q] = fma2(a23, b, c23[q]);
        }
    }

    #pragma unroll
    for (int q = 0; q < 4; q++) {
        float v0, v1, v2, v3;
        up2(v0, v1, c01[q]);
        up2(v2, v3, c23[q]);
        int base = (m0 + tm * 4) * 64 + tf * 4 + q;
        atomicAdd(&g_zacc[base          ], v0);
        atomicAdd(&g_zacc[base + 64     ], v1);
        atomicAdd(&g_zacc[base + 128    ], v2);
        atomicAdd(&g_zacc[base + 192    ], v3);
    }
}

// ---------------------------------------------------------------------------
// Kernel 3: z = relu(zacc + b1); out = z @ W2 + b2.  32 blocks x 32 rows.
// ---------------------------------------------------------------------------
__global__ void __launch_bounds__(256)
k_fc2(const float* __restrict__ fc1b, const float* __restrict__ W2,
      const float* __restrict__ fc2b, float* __restrict__ out)
{
    __shared__ float zs[32 * 64];
    __shared__ float W2s[640];
    __shared__ float b2s[10];

    const int tid = threadIdx.x;
    const int m0  = blockIdx.x * 32;

    for (int e = tid; e < 32 * 64; e += 256) {
        int f = e & 63;
        zs[e] = fmaxf(g_zacc[m0 * 64 + e] + fc1b[f], 0.f);
    }
    for (int e = tid; e < 640; e += 256) W2s[e] = W2[e];
    if (tid < 10) b2s[tid] = fc2b[tid];
    __syncthreads();

    for (int e = tid; e < 320; e += 256) {
        int m = e / 10, cc = e - m * 10;
        float s = b2s[cc];
        #pragma unroll
        for (int f = 0; f < 64; f++) s += zs[m * 64 + f] * W2s[f * 10 + cc];
        out[(m0 + m) * 10 + cc] = s;
    }
}

// ---------------------------------------------------------------------------
extern "C" void kernel_launch(void* const* d_in, const int* in_sizes, int n_in,
                              void* d_out, int out_size)
{
    (void)in_sizes; (void)n_in; (void)out_size;
    const float* x    = (const float*)d_in[0];
    const float* dtm1 = (const float*)d_in[1];
    const float* dtm2 = (const float*)d_in[2];
    const float* w1   = (const float*)d_in[3];
    const float* b1   = (const float*)d_in[4];
    const float* w2   = (const float*)d_in[5];
    const float* b2   = (const float*)d_in[6];
    const float* g1w  = (const float*)d_in[7];
    const float* g1b  = (const float*)d_in[8];
    const float* g2w  = (const float*)d_in[9];
    const float* g2b  = (const float*)d_in[10];
    const float* fc1w = (const float*)d_in[11];
    const float* fc1b = (const float*)d_in[12];
    const float* fc2w = (const float*)d_in[13];
    const float* fc2b = (const float*)d_in[14];
    float* out = (float*)d_out;

    k_fused<<<BATCH / 2, 128>>>(x, dtm1, dtm2, w1, b1, w2, b2, g1w, g1b, g2w, g2b);
    k_fc1<<<dim3(16, 16), 256>>>(fc1w);
    k_fc2<<<32, 256>>>(fc1b, fc2w, fc2b, out);
}

// round 15
// speedup vs baseline: 1.1499x; 1.0006x over previous
#include <cuda_runtime.h>
#include <cuda_bf16.h>

// Problem constants
#define BATCH    1024
#define P784     784
#define CATW     848            // 784 + 32 + 32

typedef unsigned long long ull;  // f32x2 container (two fp32 lanes per register)

// Scratch (allocation-free rule: __device__ globals)
__device__ float g_cat [BATCH * CATW];   // [1024, 848] concat rows
__device__ float g_zacc[BATCH * 64];     // fc1 pre-activation accumulator

// ---- packed f32x2 helpers (Blackwell sm_103a) ----
__device__ __forceinline__ ull pk2(float a, float b) {
    ull r; asm("mov.b64 %0, {%1, %2};" : "=l"(r) : "f"(a), "f"(b)); return r;
}
__device__ __forceinline__ void up2(float& a, float& b, ull v) {
    asm("mov.b64 {%0, %1}, %2;" : "=f"(a), "=f"(b) : "l"(v));
}
__device__ __forceinline__ ull fma2(ull a, ull b, ull c) {
    ull d; asm("fma.rn.f32x2 %0, %1, %2, %3;" : "=l"(d) : "l"(a), "l"(b), "l"(c)); return d;
}
__device__ __forceinline__ ull add2(ull a, ull b) {
    ull d; asm("add.rn.f32x2 %0, %1, %2;" : "=l"(d) : "l"(a), "l"(b)); return d;
}
__device__ __forceinline__ ull relu2(ull v) {
    float a, b; up2(a, b, v);
    return pk2(fmaxf(a, 0.f), fmaxf(b, 0.f));
}

// ---------------------------------------------------------------------------
// Kernel 1: fused conv branch + landscape branches, TWO samples per block
//   packed in f32x2 lanes. grid = 512 blocks, 128 threads (4 warps).
//   (unchanged from round 13 — measured ~7.4us — plus g_zacc zeroing)
// ---------------------------------------------------------------------------
__global__ void __launch_bounds__(128)
k_fused(const float* __restrict__ x,
        const float* __restrict__ dtm1,
        const float* __restrict__ dtm2,
        const float* __restrict__ w1g, const float* __restrict__ b1g,
        const float* __restrict__ w2g, const float* __restrict__ b2g,
        const float* __restrict__ g1w, const float* __restrict__ g1b,
        const float* __restrict__ g2w, const float* __restrict__ g2b)
{
    __shared__ __align__(16) ull w1d[32][10];     // [ch][tap0..8, 9=bias], dup pairs
    __shared__ __align__(16) ull w2d[32][10];     // [ch][tap0..8]
    __shared__ float part[4][4][3];               // (samp*2+br), warp, (m1,m2,mx)
    __shared__ float Ls[2][2][64];                // [samp][br][64]

    const int tid  = threadIdx.x;
    const int b0   = blockIdx.x * 2;
    const int b1   = b0 + 1;
    const int wid  = tid >> 5;
    const int lane = tid & 31;
    const unsigned FULL = 0xffffffffu;

    // zero fc1 accumulator rows for both samples (consumed by k_fc1)
    g_zacc[b0 * 64 + tid] = 0.f;

    // stage weights transposed + duplicated into both f32x2 lanes
    for (int i = tid; i < 288; i += 128) {
        int tap = i / 32, c = i % 32;
        float a = w1g[i], b = w2g[i];
        w1d[c][tap] = pk2(a, a);
        w2d[c][tap] = pk2(b, b);
    }
    if (tid < 32) { float v = b1g[tid]; w1d[tid][9] = pk2(v, v); }

    // ---- input rows into registers (rows r0-2 .. r0+8, zero-padded) ----
    const int r0 = wid * 7;
    const int c  = lane;
    ull xc[11], xl[11], xr[11];
    #pragma unroll
    for (int j = 0; j < 11; j++) {
        int row = r0 - 2 + j;
        float v0 = 0.f, v1 = 0.f;
        if (row >= 0 && row < 28 && c < 28) {
            v0 = x[b0 * P784 + row * 28 + c];
            v1 = x[b1 * P784 + row * 28 + c];
        }
        xc[j] = pk2(v0, v1);
    }
    #pragma unroll
    for (int j = 0; j < 11; j++) {
        ull u = __shfl_up_sync  (FULL, xc[j], 1);
        ull d = __shfl_down_sync(FULL, xc[j], 1);
        xl[j] = (lane == 0)  ? 0ULL : u;
        xr[j] = (lane >= 27) ? 0ULL : d;
    }

    // ---- landscape partial reductions (4 = 2 samples x 2 branches) ----
    #pragma unroll
    for (int pe = 0; pe < 4; pe++) {
        int samp = pe >> 1, br = pe & 1;
        const float* v = (br ? dtm2 : dtm1) + (b0 + samp) * P784;
        float m1 = 1e30f, m2 = 1e30f, mx = -1e30f;
        for (int i = tid; i < P784; i += 128) {
            float f = v[i];
            mx = fmaxf(mx, f);
            if (f < m1) { m2 = m1; m1 = f; }
            else        { m2 = fminf(m2, f); }
        }
        #pragma unroll
        for (int o = 16; o > 0; o >>= 1) {
            float o1 = __shfl_down_sync(FULL, m1, o);
            float o2 = __shfl_down_sync(FULL, m2, o);
            float ox = __shfl_down_sync(FULL, mx, o);
            float nm1 = fminf(m1, o1);
            float nm2 = fminf(fmaxf(m1, o1), fminf(m2, o2));
            m1 = nm1; m2 = nm2; mx = fmaxf(mx, ox);
        }
        if (lane == 0) { part[pe][wid][0] = m1; part[pe][wid][1] = m2; part[pe][wid][2] = mx; }
    }
    __syncthreads();   // weights + partials visible

    const float b2v = __ldg(b2g);
    ull Pa[7], Pm[7], Pb[7];
    const ull b2p = pk2(b2v, b2v);
    #pragma unroll
    for (int i = 0; i < 7; i++) { Pa[i] = 0ULL; Pm[i] = b2p; Pb[i] = 0ULL; }

    // ---- channel loop: pure register f32x2, no shuffles, no barriers ----
    #pragma unroll 1
    for (int ch = 0; ch < 32; ch++) {
        const ull* W1c = w1d[ch];
        ull h1[9];
        #pragma unroll
        for (int j = 0; j < 9; j++) {
            int row = r0 - 1 + j;
            ull s = W1c[9];
            s = fma2(xl[j    ], W1c[0], s);
            s = fma2(xc[j    ], W1c[1], s);
            s = fma2(xr[j    ], W1c[2], s);
            s = fma2(xl[j + 1], W1c[3], s);
            s = fma2(xc[j + 1], W1c[4], s);
            s = fma2(xr[j + 1], W1c[5], s);
            s = fma2(xl[j + 2], W1c[6], s);
            s = fma2(xc[j + 2], W1c[7], s);
            s = fma2(xr[j + 2], W1c[8], s);
            h1[j] = (row >= 0 && row < 28) ? relu2(s) : 0ULL;
        }
        const ull* W2c = w2d[ch];
        #pragma unroll
        for (int j = 0; j < 9; j++) {
            #pragma unroll
            for (int dr = 0; dr < 3; dr++) {
                int i = j - dr;                 // output row index
                if (i >= 0 && i < 7) {
                    Pa[i] = fma2(h1[j], W2c[dr * 3 + 0], Pa[i]);  // -> column c+1
                    Pm[i] = fma2(h1[j], W2c[dr * 3 + 1], Pm[i]);  // -> column c
                    Pb[i] = fma2(h1[j], W2c[dr * 3 + 2], Pb[i]);  // -> column c-1
                }
            }
        }
    }

    // ---- column-halo exchange ONCE + store (relu) ----
    #pragma unroll
    for (int i = 0; i < 7; i++) {
        ull au = __shfl_up_sync  (FULL, Pa[i], 1);   // from column c-1
        ull bd = __shfl_down_sync(FULL, Pb[i], 1);   // from column c+1
        ull al = (lane == 0)  ? 0ULL : au;
        ull br = (lane >= 27) ? 0ULL : bd;
        ull tot = add2(Pm[i], add2(al, br));
        if (c < 28) {
            float o0, o1; up2(o0, o1, tot);
            g_cat[b0 * CATW + (r0 + i) * 28 + c] = fmaxf(o0, 0.f);
            g_cat[b1 * CATW + (r0 + i) * 28 + c] = fmaxf(o1, 0.f);
        }
    }

    __syncthreads();   // landscape partials from all warps

    // tents: 256 values (2 samp x 2 br x 64) over 128 threads
    #pragma unroll
    for (int rep = 0; rep < 2; rep++) {
        int e = tid + rep * 128;
        int samp = e >> 7, br = (e >> 6) & 1, q = e & 63;
        int k = q >> 5, ti = q & 31;
        int pe = samp * 2 + br;
        float M1 = part[pe][0][0], M2 = part[pe][0][1], MX = part[pe][0][2];
        #pragma unroll
        for (int w = 1; w < 4; w++) {
            float a1 = part[pe][w][0], a2 = part[pe][w][1], ax = part[pe][w][2];
            float n1 = fminf(M1, a1);
            float n2 = fminf(fmaxf(M1, a1), fminf(M2, a2));
            M1 = n1; M2 = n2; MX = fmaxf(MX, ax);
        }
        float t0 = (br == 0) ? 0.01f : 0.05f;
        float dt = (br == 0) ? (0.28f / 31.0f) : (0.25f / 31.0f);
        float t  = t0 + (float)ti * dt;
        float vk = k ? M2 : M1;
        Ls[samp][br][q] = fmaxf(0.f, fminf(t - vk, MX - t));
    }
    __syncthreads();

    // branch GEMMs: 2 samples x [64] @ [64,32] + bias, relu  (128 threads)
    {
        int samp = tid >> 6, br = (tid >> 5) & 1, f = tid & 31;
        const float* gw = br ? g2w : g1w;
        float s = br ? g2b[f] : g1b[f];
        #pragma unroll
        for (int j = 0; j < 64; j++) s += Ls[samp][br][j] * gw[j * 32 + f];
        g_cat[(b0 + samp) * CATW + 784 + br * 32 + f] = fmaxf(s, 0.f);
    }
}

// ---------------------------------------------------------------------------
// Kernel 2: fc1 split-K GEMM with f32x2 m-packing.
//   [1024,848] @ [848,64] -> atomicAdd into g_zacc.
//   grid = (16 m-tiles of 64) x (16 k-chunks of 53); 256 thr.
//   Thread computes 4m x 4n as two f32x2 m-pair accumulators per n.
//   B tile pre-duplicated into both f32x2 lanes in smem.
// ---------------------------------------------------------------------------
__global__ void __launch_bounds__(256)
k_fc1(const float* __restrict__ W1)
{
    __shared__ __align__(16) float At [53 * 68];  // A^T: [k][m], stride 68
    __shared__ __align__(16) ull   Bsd[53 * 64];  // [k][f], duplicated pairs

    const int tid = threadIdx.x;
    const int m0  = blockIdx.x * 64;
    const int k0  = blockIdx.y * 53;
    const int tm  = tid & 15;
    const int tf  = tid >> 4;

    for (int e = tid; e < 53 * 64; e += 256) {
        int i = e / 53, j = e - i * 53;
        At[j * 68 + i] = g_cat[(m0 + i) * CATW + k0 + j];
    }
    for (int e = tid; e < 53 * 64; e += 256) {
        int j = e >> 6, q = e & 63;
        float w = W1[(k0 + j) * 64 + q];        // coalesced
        Bsd[j * 64 + q] = pk2(w, w);
    }
    __syncthreads();

    ull c01[4] = {0ULL, 0ULL, 0ULL, 0ULL};
    ull c23[4] = {0ULL, 0ULL, 0ULL, 0ULL};
    #pragma unroll 4
    for (int k = 0; k < 53; k++) {
        float4 a = *(const float4*)&At[k * 68 + tm * 4];
        ull a01 = pk2(a.x, a.y);
        ull a23 = pk2(a.z, a.w);
        const ull* bp = &Bsd[k * 64 + tf * 4];
        #pragma unroll
        for (int q = 0; q < 4; q++) {
            ull b = bp[q];                       // broadcast LDS
            c01[q] = fma2(a01, b, c01[q]);
            c23[q] = fma2(a23, b, c23[q]);
        }
    }

    #pragma unroll
    for (int q = 0; q < 4; q++) {
        float v0, v1, v2, v3;
        up2(v0, v1, c01[q]);
        up2(v2, v3, c23[q]);
        int base = (m0 + tm * 4) * 64 + tf * 4 + q;
        atomicAdd(&g_zacc[base          ], v0);
        atomicAdd(&g_zacc[base + 64     ], v1);
        atomicAdd(&g_zacc[base + 128    ], v2);
        atomicAdd(&g_zacc[base + 192    ], v3);
    }
}

// ---------------------------------------------------------------------------
// Kernel 3: z = relu(zacc + b1); out = z @ W2 + b2.  32 blocks x 32 rows.
// ---------------------------------------------------------------------------
__global__ void __launch_bounds__(256)
k_fc2(const float* __restrict__ fc1b, const float* __restrict__ W2,
      const float* __restrict__ fc2b, float* __restrict__ out)
{
    __shared__ float zs[32 * 64];
    __shared__ float W2s[640];
    __shared__ float b2s[10];

    const int tid = threadIdx.x;
    const int m0  = blockIdx.x * 32;

    for (int e = tid; e < 32 * 64; e += 256) {
        int f = e & 63;
        zs[e] = fmaxf(g_zacc[m0 * 64 + e] + fc1b[f], 0.f);
    }
    for (int e = tid; e < 640; e += 256) W2s[e] = W2[e];
    if (tid < 10) b2s[tid] = fc2b[tid];
    __syncthreads();

    for (int e = tid; e < 320; e += 256) {
        int m = e / 10, cc = e - m * 10;
        float s = b2s[cc];
        #pragma unroll
        for (int f = 0; f < 64; f++) s += zs[m * 64 + f] * W2s[f * 10 + cc];
        out[(m0 + m) * 10 + cc] = s;
    }
}

// ---------------------------------------------------------------------------
extern "C" void kernel_launch(void* const* d_in, const int* in_sizes, int n_in,
                              void* d_out, int out_size)
{
    (void)in_sizes; (void)n_in; (void)out_size;
    const float* x    = (const float*)d_in[0];
    const float* dtm1 = (const float*)d_in[1];
    const float* dtm2 = (const float*)d_in[2];
    const float* w1   = (const float*)d_in[3];
    const float* b1   = (const float*)d_in[4];
    const float* w2   = (const float*)d_in[5];
    const float* b2   = (const float*)d_in[6];
    const float* g1w  = (const float*)d_in[7];
    const float* g1b  = (const float*)d_in[8];
    const float* g2w  = (const float*)d_in[9];
    const float* g2b  = (const float*)d_in[10];
    const float* fc1w = (const float*)d_in[11];
    const float* fc1b = (const float*)d_in[12];
    const float* fc2w = (const float*)d_in[13];
    const float* fc2b = (const float*)d_in[14];
    float* out = (float*)d_out;

    k_fused<<<BATCH / 2, 128>>>(x, dtm1, dtm2, w1, b1, w2, b2, g1w, g1b, g2w, g2b);
    k_fc1<<<dim3(16, 16), 256>>>(fc1w);
    k_fc2<<<32, 256>>>(fc1b, fc2w, fc2b, out);
}

// round 16
// speedup vs baseline: 1.1829x; 1.0287x over previous
#include <cuda_runtime.h>
#include <cuda_bf16.h>

// Problem constants
#define BATCH    1024
#define P784     784
#define CATW     848            // 784 + 32 + 32

typedef unsigned long long ull;  // f32x2 container (two fp32 lanes per register)

// Scratch (allocation-free rule: __device__/__constant__ globals)
__device__ float g_cat [BATCH * CATW];   // [1024, 848] concat rows
__device__ float g_zacc[BATCH * 64];     // fc1 pre-activation accumulator
__device__ ull   g_wstage[640];          // packed conv weights staging
__constant__ ull c_wall[640];            // [ch*10+t]=w1 taps0-8,bias | 320+[ch*10+t]=w2

// ---- packed f32x2 helpers (Blackwell sm_103a) ----
__device__ __forceinline__ ull pk2(float a, float b) {
    ull r; asm("mov.b64 %0, {%1, %2};" : "=l"(r) : "f"(a), "f"(b)); return r;
}
__device__ __forceinline__ void up2(float& a, float& b, ull v) {
    asm("mov.b64 {%0, %1}, %2;" : "=f"(a), "=f"(b) : "l"(v));
}
__device__ __forceinline__ ull fma2(ull a, ull b, ull c) {
    ull d; asm("fma.rn.f32x2 %0, %1, %2, %3;" : "=l"(d) : "l"(a), "l"(b), "l"(c)); return d;
}
__device__ __forceinline__ ull add2(ull a, ull b) {
    ull d; asm("add.rn.f32x2 %0, %1, %2;" : "=l"(d) : "l"(a), "l"(b)); return d;
}
__device__ __forceinline__ ull relu2(ull v) {
    float a, b; up2(a, b, v);
    return pk2(fmaxf(a, 0.f), fmaxf(b, 0.f));
}

// ---------------------------------------------------------------------------
// Kernel 0: pack conv weights (f32x2-duplicated) into staging buffer.
//   Copied to __constant__ c_wall by an async D2D memcpy in kernel_launch.
// ---------------------------------------------------------------------------
__global__ void k_prep(const float* __restrict__ w1, const float* __restrict__ b1,
                       const float* __restrict__ w2)
{
    int i = threadIdx.x;              // 0..319
    int ch = i / 10, t = i - ch * 10;
    float v1 = (t < 9) ? w1[t * 32 + ch] : b1[ch];
    float v2 = (t < 9) ? w2[t * 32 + ch] : 0.f;
    g_wstage[      ch * 10 + t] = pk2(v1, v1);
    g_wstage[320 + ch * 10 + t] = pk2(v2, v2);
}

// ---------------------------------------------------------------------------
// Kernel 1: fused conv branch + landscape branches, TWO samples per block
//   packed in f32x2 lanes. grid = 512 blocks, 128 threads (4 warps).
//   Weights come from __constant__ (uniform LDCU path: zero GPR cost, zero
//   LSU traffic). conv1/conv2 merged per-row: h1 liveness = 1 value.
//   landscape: tent(v,t) monotone non-increasing in v => only (min1,min2,max).
// ---------------------------------------------------------------------------
__global__ void __launch_bounds__(128, 4)
k_fused(const float* __restrict__ x,
        const float* __restrict__ dtm1,
        const float* __restrict__ dtm2,
        const float* __restrict__ g1w, const float* __restrict__ g1b,
        const float* __restrict__ g2w, const float* __restrict__ g2b,
        const float* __restrict__ b2g)
{
    __shared__ float part[4][4][3];               // (samp*2+br), warp, (m1,m2,mx)
    __shared__ float Ls[2][2][64];                // [samp][br][64]

    const int tid  = threadIdx.x;
    const int b0   = blockIdx.x * 2;
    const int b1   = b0 + 1;
    const int wid  = tid >> 5;
    const int lane = tid & 31;
    const unsigned FULL = 0xffffffffu;

    // zero fc1 accumulator rows for both samples (consumed by k_fc1)
    g_zacc[b0 * 64 + tid] = 0.f;

    // ---- input rows into registers (rows r0-2 .. r0+8, zero-padded) ----
    const int r0 = wid * 7;
    const int c  = lane;
    ull xc[11], xl[11], xr[11];
    #pragma unroll
    for (int j = 0; j < 11; j++) {
        int row = r0 - 2 + j;
        float v0 = 0.f, v1 = 0.f;
        if (row >= 0 && row < 28 && c < 28) {
            v0 = x[b0 * P784 + row * 28 + c];
            v1 = x[b1 * P784 + row * 28 + c];
        }
        xc[j] = pk2(v0, v1);
    }
    #pragma unroll
    for (int j = 0; j < 11; j++) {
        ull u = __shfl_up_sync  (FULL, xc[j], 1);
        ull d = __shfl_down_sync(FULL, xc[j], 1);
        xl[j] = (lane == 0)  ? 0ULL : u;
        xr[j] = (lane >= 27) ? 0ULL : d;
    }

    // ---- landscape partial reductions (4 = 2 samples x 2 branches) ----
    #pragma unroll
    for (int pe = 0; pe < 4; pe++) {
        int samp = pe >> 1, br = pe & 1;
        const float* v = (br ? dtm2 : dtm1) + (b0 + samp) * P784;
        float m1 = 1e30f, m2 = 1e30f, mx = -1e30f;
        for (int i = tid; i < P784; i += 128) {
            float f = v[i];
            mx = fmaxf(mx, f);
            if (f < m1) { m2 = m1; m1 = f; }
            else        { m2 = fminf(m2, f); }
        }
        #pragma unroll
        for (int o = 16; o > 0; o >>= 1) {
            float o1 = __shfl_down_sync(FULL, m1, o);
            float o2 = __shfl_down_sync(FULL, m2, o);
            float ox = __shfl_down_sync(FULL, mx, o);
            float nm1 = fminf(m1, o1);
            float nm2 = fminf(fmaxf(m1, o1), fminf(m2, o2));
            m1 = nm1; m2 = nm2; mx = fmaxf(mx, ox);
        }
        if (lane == 0) { part[pe][wid][0] = m1; part[pe][wid][1] = m2; part[pe][wid][2] = mx; }
    }

    const float b2v = __ldg(b2g);
    ull Pa[7], Pm[7], Pb[7];
    const ull b2p = pk2(b2v, b2v);
    #pragma unroll
    for (int i = 0; i < 7; i++) { Pa[i] = 0ULL; Pm[i] = b2p; Pb[i] = 0ULL; }

    // ---- channel loop: conv1+conv2 merged per h1 row; weights via LDCU ----
    #pragma unroll 1
    for (int ch = 0; ch < 32; ch++) {
        const ull* W1c = &c_wall[ch * 10];
        const ull* W2c = &c_wall[320 + ch * 10];
        #pragma unroll
        for (int j = 0; j < 9; j++) {
            int row = r0 - 1 + j;
            ull s = W1c[9];
            s = fma2(xl[j    ], W1c[0], s);
            s = fma2(xc[j    ], W1c[1], s);
            s = fma2(xr[j    ], W1c[2], s);
            s = fma2(xl[j + 1], W1c[3], s);
            s = fma2(xc[j + 1], W1c[4], s);
            s = fma2(xr[j + 1], W1c[5], s);
            s = fma2(xl[j + 2], W1c[6], s);
            s = fma2(xc[j + 2], W1c[7], s);
            s = fma2(xr[j + 2], W1c[8], s);
            ull h = (row >= 0 && row < 28) ? relu2(s) : 0ULL;
            // consume immediately: output rows i = j-dr, taps dr = j-i
            #pragma unroll
            for (int dr = 0; dr < 3; dr++) {
                int i = j - dr;
                if (i >= 0 && i < 7) {
                    Pa[i] = fma2(h, W2c[dr * 3 + 0], Pa[i]);  // -> column c+1
                    Pm[i] = fma2(h, W2c[dr * 3 + 1], Pm[i]);  // -> column c
                    Pb[i] = fma2(h, W2c[dr * 3 + 2], Pb[i]);  // -> column c-1
                }
            }
        }
    }

    // ---- column-halo exchange ONCE + store (relu) ----
    #pragma unroll
    for (int i = 0; i < 7; i++) {
        ull au = __shfl_up_sync  (FULL, Pa[i], 1);   // from column c-1
        ull bd = __shfl_down_sync(FULL, Pb[i], 1);   // from column c+1
        ull al = (lane == 0)  ? 0ULL : au;
        ull br = (lane >= 27) ? 0ULL : bd;
        ull tot = add2(Pm[i], add2(al, br));
        if (c < 28) {
            float o0, o1; up2(o0, o1, tot);
            g_cat[b0 * CATW + (r0 + i) * 28 + c] = fmaxf(o0, 0.f);
            g_cat[b1 * CATW + (r0 + i) * 28 + c] = fmaxf(o1, 0.f);
        }
    }

    __syncthreads();   // landscape partials from all warps

    // tents: 256 values (2 samp x 2 br x 64) over 128 threads
    #pragma unroll
    for (int rep = 0; rep < 2; rep++) {
        int e = tid + rep * 128;
        int samp = e >> 7, br = (e >> 6) & 1, q = e & 63;
        int k = q >> 5, ti = q & 31;
        int pe = samp * 2 + br;
        float M1 = part[pe][0][0], M2 = part[pe][0][1], MX = part[pe][0][2];
        #pragma unroll
        for (int w = 1; w < 4; w++) {
            float a1 = part[pe][w][0], a2 = part[pe][w][1], ax = part[pe][w][2];
            float n1 = fminf(M1, a1);
            float n2 = fminf(fmaxf(M1, a1), fminf(M2, a2));
            M1 = n1; M2 = n2; MX = fmaxf(MX, ax);
        }
        float t0 = (br == 0) ? 0.01f : 0.05f;
        float dt = (br == 0) ? (0.28f / 31.0f) : (0.25f / 31.0f);
        float t  = t0 + (float)ti * dt;
        float vk = k ? M2 : M1;
        Ls[samp][br][q] = fmaxf(0.f, fminf(t - vk, MX - t));
    }
    __syncthreads();

    // branch GEMMs: 2 samples x [64] @ [64,32] + bias, relu  (128 threads)
    {
        int samp = tid >> 6, br = (tid >> 5) & 1, f = tid & 31;
        const float* gw = br ? g2w : g1w;
        float s = br ? g2b[f] : g1b[f];
        #pragma unroll
        for (int j = 0; j < 64; j++) s += Ls[samp][br][j] * gw[j * 32 + f];
        g_cat[(b0 + samp) * CATW + 784 + br * 32 + f] = fmaxf(s, 0.f);
    }
}

// ---------------------------------------------------------------------------
// Kernel 2: fc1 split-K GEMM with f32x2 m-packing.
//   [1024,848] @ [848,64] -> atomicAdd into g_zacc.
//   grid = (16 m-tiles of 64) x (16 k-chunks of 53); 256 thr.
// ---------------------------------------------------------------------------
__global__ void __launch_bounds__(256)
k_fc1(const float* __restrict__ W1)
{
    __shared__ __align__(16) float At [53 * 68];  // A^T: [k][m], stride 68
    __shared__ __align__(16) ull   Bsd[53 * 64];  // [k][f], duplicated pairs

    const int tid = threadIdx.x;
    const int m0  = blockIdx.x * 64;
    const int k0  = blockIdx.y * 53;
    const int tm  = tid & 15;
    const int tf  = tid >> 4;

    for (int e = tid; e < 53 * 64; e += 256) {
        int i = e / 53, j = e - i * 53;
        At[j * 68 + i] = g_cat[(m0 + i) * CATW + k0 + j];
    }
    for (int e = tid; e < 53 * 64; e += 256) {
        int j = e >> 6, q = e & 63;
        float w = W1[(k0 + j) * 64 + q];        // coalesced
        Bsd[j * 64 + q] = pk2(w, w);
    }
    __syncthreads();

    ull c01[4] = {0ULL, 0ULL, 0ULL, 0ULL};
    ull c23[4] = {0ULL, 0ULL, 0ULL, 0ULL};
    #pragma unroll 4
    for (int k = 0; k < 53; k++) {
        float4 a = *(const float4*)&At[k * 68 + tm * 4];
        ull a01 = pk2(a.x, a.y);
        ull a23 = pk2(a.z, a.w);
        const ull* bp = &Bsd[k * 64 + tf * 4];
        #pragma unroll
        for (int q = 0; q < 4; q++) {
            ull b = bp[q];                       // broadcast LDS
            c01[q] = fma2(a01, b, c01[q]);
            c23[q] = fma2(a23, b, c23[q]);
        }
    }

    #pragma unroll
    for (int q = 0; q < 4; q++) {
        float v0, v1, v2, v3;
        up2(v0, v1, c01[q]);
        up2(v2, v3, c23[q]);
        int base = (m0 + tm * 4) * 64 + tf * 4 + q;
        atomicAdd(&g_zacc[base      ], v0);
        atomicAdd(&g_zacc[base + 64 ], v1);
        atomicAdd(&g_zacc[base + 128], v2);
        atomicAdd(&g_zacc[base + 192], v3);
    }
}

// ---------------------------------------------------------------------------
// Kernel 3: z = relu(zacc + b1); out = z @ W2 + b2.  32 blocks x 32 rows.
// ---------------------------------------------------------------------------
__global__ void __launch_bounds__(256)
k_fc2(const float* __restrict__ fc1b, const float* __restrict__ W2,
      const float* __restrict__ fc2b, float* __restrict__ out)
{
    __shared__ float zs[32 * 64];
    __shared__ float W2s[640];
    __shared__ float b2s[10];

    const int tid = threadIdx.x;
    const int m0  = blockIdx.x * 32;

    for (int e = tid; e < 32 * 64; e += 256) {
        int f = e & 63;
        zs[e] = fmaxf(g_zacc[m0 * 64 + e] + fc1b[f], 0.f);
    }
    for (int e = tid; e < 640; e += 256) W2s[e] = W2[e];
    if (tid < 10) b2s[tid] = fc2b[tid];
    __syncthreads();

    for (int e = tid; e < 320; e += 256) {
        int m = e / 10, cc = e - m * 10;
        float s = b2s[cc];
        #pragma unroll
        for (int f = 0; f < 64; f++) s += zs[m * 64 + f] * W2s[f * 10 + cc];
        out[(m0 + m) * 10 + cc] = s;
    }
}

// ---------------------------------------------------------------------------
extern "C" void kernel_launch(void* const* d_in, const int* in_sizes, int n_in,
                              void* d_out, int out_size)
{
    (void)in_sizes; (void)n_in; (void)out_size;
    const float* x    = (const float*)d_in[0];
    const float* dtm1 = (const float*)d_in[1];
    const float* dtm2 = (const float*)d_in[2];
    const float* w1   = (const float*)d_in[3];
    const float* b1   = (const float*)d_in[4];
    const float* w2   = (const float*)d_in[5];
    const float* b2   = (const float*)d_in[6];
    const float* g1w  = (const float*)d_in[7];
    const float* g1b  = (const float*)d_in[8];
    const float* g2w  = (const float*)d_in[9];
    const float* g2b  = (const float*)d_in[10];
    const float* fc1w = (const float*)d_in[11];
    const float* fc1b = (const float*)d_in[12];
    const float* fc2w = (const float*)d_in[13];
    const float* fc2b = (const float*)d_in[14];
    float* out = (float*)d_out;

    // pack weights, then async D2D copy into __constant__ (graph-capturable)
    k_prep<<<1, 320>>>(w1, b1, w2);
    void* stage_ptr = nullptr;
    cudaGetSymbolAddress(&stage_ptr, g_wstage);
    cudaMemcpyToSymbolAsync(c_wall, stage_ptr, 640 * sizeof(ull), 0,
                            cudaMemcpyDeviceToDevice, 0);

    k_fused<<<BATCH / 2, 128>>>(x, dtm1, dtm2, g1w, g1b, g2w, g2b, b2);
    k_fc1<<<dim3(16, 16), 256>>>(fc1w);
    k_fc2<<<32, 256>>>(fc1b, fc2w, fc2b, out);
}

// round 17
// speedup vs baseline: 1.2287x; 1.0387x over previous
#include <cuda_runtime.h>
#include <cuda_bf16.h>

// Problem constants
#define BATCH    1024
#define P784     784
#define CATW     848            // 784 + 32 + 32

typedef unsigned long long ull;  // f32x2 container (two fp32 lanes per register)

// Scratch (allocation-free rule: __device__/__constant__ globals)
__device__ float g_cat [BATCH * CATW];   // [1024, 848] concat rows
__device__ float g_zacc[BATCH * 64];     // fc1 pre-activation accumulator
__device__ ull   g_wstage[640];          // packed conv weights staging
__constant__ ull c_wall[640];            // [ch*10+t]=w1 taps0-8,bias | 320+: w2

// ---- packed f32x2 helpers (Blackwell sm_103a) ----
__device__ __forceinline__ ull pk2(float a, float b) {
    ull r; asm("mov.b64 %0, {%1, %2};" : "=l"(r) : "f"(a), "f"(b)); return r;
}
__device__ __forceinline__ void up2(float& a, float& b, ull v) {
    asm("mov.b64 {%0, %1}, %2;" : "=f"(a), "=f"(b) : "l"(v));
}
__device__ __forceinline__ ull fma2(ull a, ull b, ull c) {
    ull d; asm("fma.rn.f32x2 %0, %1, %2, %3;" : "=l"(d) : "l"(a), "l"(b), "l"(c)); return d;
}
__device__ __forceinline__ ull mul2(ull a, ull b) {
    ull d; asm("mul.rn.f32x2 %0, %1, %2;" : "=l"(d) : "l"(a), "l"(b)); return d;
}
__device__ __forceinline__ ull add2(ull a, ull b) {
    ull d; asm("add.rn.f32x2 %0, %1, %2;" : "=l"(d) : "l"(a), "l"(b)); return d;
}
__device__ __forceinline__ ull relu2(ull v) {
    float a, b; up2(a, b, v);
    return pk2(fmaxf(a, 0.f), fmaxf(b, 0.f));
}

// ---------------------------------------------------------------------------
// Kernel 0: pack conv weights (f32x2-duplicated) into staging buffer.
// ---------------------------------------------------------------------------
__global__ void k_prep(const float* __restrict__ w1, const float* __restrict__ b1,
                       const float* __restrict__ w2)
{
    int i = threadIdx.x;              // 0..319
    int ch = i / 10, t = i - ch * 10;
    float v1 = (t < 9) ? w1[t * 32 + ch] : b1[ch];
    float v2 = (t < 9) ? w2[t * 32 + ch] : 0.f;
    g_wstage[      ch * 10 + t] = pk2(v1, v1);
    g_wstage[320 + ch * 10 + t] = pk2(v2, v2);
}

// ---------------------------------------------------------------------------
// Kernel 1: landscape branches + tents + branch GEMVs + g_zacc zeroing.
//   grid = 1024 blocks (1 per sample), 128 threads.
//   landscape: tent(v,t) monotone non-increasing in v => only (min1,min2,max).
// ---------------------------------------------------------------------------
__global__ void __launch_bounds__(128)
k_land(const float* __restrict__ dtm1, const float* __restrict__ dtm2,
       const float* __restrict__ g1w, const float* __restrict__ g1b,
       const float* __restrict__ g2w, const float* __restrict__ g2b)
{
    __shared__ float part[2][4][3];   // branch, warp, (m1,m2,mx)
    __shared__ float Ls[2][64];

    const int tid  = threadIdx.x;
    const int b    = blockIdx.x;
    const int wid  = tid >> 5;
    const int lane = tid & 31;
    const unsigned FULL = 0xffffffffu;

    if (tid < 64) g_zacc[b * 64 + tid] = 0.f;

    #pragma unroll
    for (int br = 0; br < 2; br++) {
        const float* v = (br ? dtm2 : dtm1) + b * P784;
        float m1 = 1e30f, m2 = 1e30f, mx = -1e30f;
        for (int i = tid; i < P784; i += 128) {
            float f = v[i];
            mx = fmaxf(mx, f);
            if (f < m1) { m2 = m1; m1 = f; }
            else        { m2 = fminf(m2, f); }
        }
        #pragma unroll
        for (int o = 16; o > 0; o >>= 1) {
            float o1 = __shfl_down_sync(FULL, m1, o);
            float o2 = __shfl_down_sync(FULL, m2, o);
            float ox = __shfl_down_sync(FULL, mx, o);
            float nm1 = fminf(m1, o1);
            float nm2 = fminf(fmaxf(m1, o1), fminf(m2, o2));
            m1 = nm1; m2 = nm2; mx = fmaxf(mx, ox);
        }
        if (lane == 0) { part[br][wid][0] = m1; part[br][wid][1] = m2; part[br][wid][2] = mx; }
    }
    __syncthreads();

    // tents: 128 threads -> Ls[2][64]
    {
        int br = tid >> 6, q = tid & 63;
        int k = q >> 5, ti = q & 31;
        float M1 = part[br][0][0], M2 = part[br][0][1], MX = part[br][0][2];
        #pragma unroll
        for (int w = 1; w < 4; w++) {
            float a1 = part[br][w][0], a2 = part[br][w][1], ax = part[br][w][2];
            float n1 = fminf(M1, a1);
            float n2 = fminf(fmaxf(M1, a1), fminf(M2, a2));
            M1 = n1; M2 = n2; MX = fmaxf(MX, ax);
        }
        float t0 = (br == 0) ? 0.01f : 0.05f;
        float dt = (br == 0) ? (0.28f / 31.0f) : (0.25f / 31.0f);
        float t  = t0 + (float)ti * dt;
        float vk = k ? M2 : M1;
        Ls[br][q] = fmaxf(0.f, fminf(t - vk, MX - t));
    }
    __syncthreads();

    // branch GEMVs: [64] @ [64,32] + bias, relu
    if (tid < 64) {
        int br = tid >> 5, f = tid & 31;
        const float* gw = br ? g2w : g1w;
        float s = br ? g2b[f] : g1b[f];
        #pragma unroll
        for (int j = 0; j < 64; j++) s += Ls[br][j] * gw[j * 32 + f];
        g_cat[b * CATW + 784 + br * 32 + f] = fmaxf(s, 0.f);
    }
}

// ---------------------------------------------------------------------------
// Kernel 2: conv branch ONLY, TWO samples per block in f32x2 lanes.
//   grid = 512 blocks, 128 threads (4 warps). Zero smem, zero barriers.
//   Warp w owns output rows [7w, 7w+7); lane = column (lanes 28-31 idle).
//   Weights via __constant__ (uniform path). conv1 row split into 3
//   independent FMA chains for ILP. conv2 accumulates Pa/Pm/Pb partials;
//   column halos exchanged by shuffle once at the end.
// ---------------------------------------------------------------------------
__global__ void __launch_bounds__(128, 4)
k_conv(const float* __restrict__ x, const float* __restrict__ b2g)
{
    const int tid  = threadIdx.x;
    const int b0   = blockIdx.x * 2;
    const int b1   = b0 + 1;
    const int wid  = tid >> 5;
    const int lane = tid & 31;
    const unsigned FULL = 0xffffffffu;

    // ---- input rows into registers (rows r0-2 .. r0+8, zero-padded) ----
    const int r0 = wid * 7;
    const int c  = lane;
    ull xc[11], xl[11], xr[11];
    #pragma unroll
    for (int j = 0; j < 11; j++) {
        int row = r0 - 2 + j;
        float v0 = 0.f, v1 = 0.f;
        if (row >= 0 && row < 28 && c < 28) {
            v0 = x[b0 * P784 + row * 28 + c];
            v1 = x[b1 * P784 + row * 28 + c];
        }
        xc[j] = pk2(v0, v1);
    }
    #pragma unroll
    for (int j = 0; j < 11; j++) {
        ull u = __shfl_up_sync  (FULL, xc[j], 1);
        ull d = __shfl_down_sync(FULL, xc[j], 1);
        xl[j] = (lane == 0)  ? 0ULL : u;
        xr[j] = (lane >= 27) ? 0ULL : d;
    }

    const float b2v = __ldg(b2g);
    ull Pa[7], Pm[7], Pb[7];
    const ull b2p = pk2(b2v, b2v);
    #pragma unroll
    for (int i = 0; i < 7; i++) { Pa[i] = 0ULL; Pm[i] = b2p; Pb[i] = 0ULL; }

    // ---- channel loop: conv1 (3 independent chains/row) + fused conv2 ----
    #pragma unroll 1
    for (int ch = 0; ch < 32; ch++) {
        const ull* W1c = &c_wall[ch * 10];
        const ull* W2c = &c_wall[320 + ch * 10];
        #pragma unroll
        for (int j = 0; j < 9; j++) {
            int row = r0 - 1 + j;
            // three independent chains (depth 3) instead of one depth-9 chain
            ull s0 = fma2(xr[j    ], W1c[2], fma2(xc[j    ], W1c[1], mul2(xl[j    ], W1c[0])));
            ull s1 = fma2(xr[j + 1], W1c[5], fma2(xc[j + 1], W1c[4], fma2(xl[j + 1], W1c[3], W1c[9])));
            ull s2 = fma2(xr[j + 2], W1c[8], fma2(xc[j + 2], W1c[7], mul2(xl[j + 2], W1c[6])));
            ull s  = add2(s1, add2(s0, s2));
            ull h  = (row >= 0 && row < 28) ? relu2(s) : 0ULL;
            // consume immediately: output rows i = j-dr
            #pragma unroll
            for (int dr = 0; dr < 3; dr++) {
                int i = j - dr;
                if (i >= 0 && i < 7) {
                    Pa[i] = fma2(h, W2c[dr * 3 + 0], Pa[i]);  // -> column c+1
                    Pm[i] = fma2(h, W2c[dr * 3 + 1], Pm[i]);  // -> column c
                    Pb[i] = fma2(h, W2c[dr * 3 + 2], Pb[i]);  // -> column c-1
                }
            }
        }
    }

    // ---- column-halo exchange ONCE + store (relu) ----
    #pragma unroll
    for (int i = 0; i < 7; i++) {
        ull au = __shfl_up_sync  (FULL, Pa[i], 1);   // from column c-1
        ull bd = __shfl_down_sync(FULL, Pb[i], 1);   // from column c+1
        ull al = (lane == 0)  ? 0ULL : au;
        ull br = (lane >= 27) ? 0ULL : bd;
        ull tot = add2(Pm[i], add2(al, br));
        if (c < 28) {
            float o0, o1; up2(o0, o1, tot);
            g_cat[b0 * CATW + (r0 + i) * 28 + c] = fmaxf(o0, 0.f);
            g_cat[b1 * CATW + (r0 + i) * 28 + c] = fmaxf(o1, 0.f);
        }
    }
}

// ---------------------------------------------------------------------------
// Kernel 3: fc1 split-K GEMM with f32x2 m-packing.
//   [1024,848] @ [848,64] -> atomicAdd into g_zacc.
//   grid = (16 m-tiles of 64) x (16 k-chunks of 53); 256 thr.
// ---------------------------------------------------------------------------
__global__ void __launch_bounds__(256)
k_fc1(const float* __restrict__ W1)
{
    __shared__ __align__(16) float At [53 * 68];  // A^T: [k][m], stride 68
    __shared__ __align__(16) ull   Bsd[53 * 64];  // [k][f], duplicated pairs

    const int tid = threadIdx.x;
    const int m0  = blockIdx.x * 64;
    const int k0  = blockIdx.y * 53;
    const int tm  = tid & 15;
    const int tf  = tid >> 4;

    for (int e = tid; e < 53 * 64; e += 256) {
        int i = e / 53, j = e - i * 53;
        At[j * 68 + i] = g_cat[(m0 + i) * CATW + k0 + j];
    }
    for (int e = tid; e < 53 * 64; e += 256) {
        int j = e >> 6, q = e & 63;
        float w = W1[(k0 + j) * 64 + q];        // coalesced
        Bsd[j * 64 + q] = pk2(w, w);
    }
    __syncthreads();

    ull c01[4] = {0ULL, 0ULL, 0ULL, 0ULL};
    ull c23[4] = {0ULL, 0ULL, 0ULL, 0ULL};
    #pragma unroll 4
    for (int k = 0; k < 53; k++) {
        float4 a = *(const float4*)&At[k * 68 + tm * 4];
        ull a01 = pk2(a.x, a.y);
        ull a23 = pk2(a.z, a.w);
        const ull* bp = &Bsd[k * 64 + tf * 4];
        #pragma unroll
        for (int q = 0; q < 4; q++) {
            ull b = bp[q];                       // broadcast LDS
            c01[q] = fma2(a01, b, c01[q]);
            c23[q] = fma2(a23, b, c23[q]);
        }
    }

    #pragma unroll
    for (int q = 0; q < 4; q++) {
        float v0, v1, v2, v3;
        up2(v0, v1, c01[q]);
        up2(v2, v3, c23[q]);
        int base = (m0 + tm * 4) * 64 + tf * 4 + q;
        atomicAdd(&g_zacc[base      ], v0);
        atomicAdd(&g_zacc[base + 64 ], v1);
        atomicAdd(&g_zacc[base + 128], v2);
        atomicAdd(&g_zacc[base + 192], v3);
    }
}

// ---------------------------------------------------------------------------
// Kernel 4: out = relu(zacc + b1) @ W2 + b2, split-K over 4 lanes/output.
//   grid = 128 blocks x 320 threads; thread = (output o, k-quarter kq).
// ---------------------------------------------------------------------------
__global__ void __launch_bounds__(320)
k_fc2(const float* __restrict__ fc1b, const float* __restrict__ W2,
      const float* __restrict__ fc2b, float* __restrict__ out)
{
    const int tid = threadIdx.x;
    const int o   = tid >> 2;          // 0..79 outputs per block
    const int kq  = tid & 3;           // k-quarter
    const int m   = blockIdx.x * 8 + o / 10;
    const int cc  = o % 10;

    const float* za = &g_zacc[m * 64 + kq * 16];
    const float* bb = &fc1b[kq * 16];

    float s = 0.f;
    #pragma unroll
    for (int i = 0; i < 16; i++) {
        int f = kq * 16 + i;
        float z = fmaxf(za[i] + bb[i], 0.f);
        s += z * W2[f * 10 + cc];
    }
    s += __shfl_xor_sync(0xffffffffu, s, 1);
    s += __shfl_xor_sync(0xffffffffu, s, 2);
    if (kq == 0) out[m * 10 + cc] = s + fc2b[cc];
}

// ---------------------------------------------------------------------------
extern "C" void kernel_launch(void* const* d_in, const int* in_sizes, int n_in,
                              void* d_out, int out_size)
{
    (void)in_sizes; (void)n_in; (void)out_size;
    const float* x    = (const float*)d_in[0];
    const float* dtm1 = (const float*)d_in[1];
    const float* dtm2 = (const float*)d_in[2];
    const float* w1   = (const float*)d_in[3];
    const float* b1   = (const float*)d_in[4];
    const float* w2   = (const float*)d_in[5];
    const float* b2   = (const float*)d_in[6];
    const float* g1w  = (const float*)d_in[7];
    const float* g1b  = (const float*)d_in[8];
    const float* g2w  = (const float*)d_in[9];
    const float* g2b  = (const float*)d_in[10];
    const float* fc1w = (const float*)d_in[11];
    const float* fc1b = (const float*)d_in[12];
    const float* fc2w = (const float*)d_in[13];
    const float* fc2b = (const float*)d_in[14];
    float* out = (float*)d_out;

    // pack weights, then async D2D copy into __constant__ (graph-capturable)
    k_prep<<<1, 320>>>(w1, b1, w2);
    void* stage_ptr = nullptr;
    cudaGetSymbolAddress(&stage_ptr, g_wstage);
    cudaMemcpyToSymbolAsync(c_wall, stage_ptr, 640 * sizeof(ull), 0,
                            cudaMemcpyDeviceToDevice, 0);

    k_land<<<BATCH, 128>>>(dtm1, dtm2, g1w, g1b, g2w, g2b);
    k_conv<<<BATCH / 2, 128>>>(x, b2);
    k_fc1<<<dim3(16, 16), 256>>>(fc1w);
    k_fc2<<<BATCH / 8, 320>>>(fc1b, fc2w, fc2b, out);
}